// round 13
// baseline (speedup 1.0000x reference)
#include <cuda_runtime.h>
#include <cuda_bf16.h>
#include <cstdint>

// ---------------------------------------------------------------------------
// ConvAttention, R11: inline (recomputed) fill descriptors to kill register
// spills in convmma; smem-staged coalesced prep_wt. 3-stream DAG as R10.
// ---------------------------------------------------------------------------

#define Bn   8
#define T1n  800
#define T2n  200

// -------- scratch (device globals; zero-initialized, guards never written) --
__device__ __nv_bfloat16 g_xt [1664 * 512];      // keys guarded [1609+pad][512]
__device__ __nv_bfloat16 g_xq [6528 * 128];      // queries guarded [6409+pad][128]
__device__ __nv_bfloat16 g_h1 [1664 * 1024];     // kp1 out, guard layout
__device__ __nv_bfloat16 g_keb[1600 * 128];      // key emb plain (pads stay 0)
__device__ __nv_bfloat16 g_hq1[6528 * 192];      // qp1 out, guard layout
__device__ __nv_bfloat16 g_hq2[6400 * 128];      // qp2 out plain
__device__ __nv_bfloat16 g_qeb[6400 * 128];      // query emb plain
__device__ __nv_bfloat16 g_wt [3 * 1024 * 512];  // kp_w1 [tap][m][512]
__device__ __nv_bfloat16 g_wk2[80 * 1024];
__device__ __nv_bfloat16 g_wq1[3 * 160 * 128];
__device__ __nv_bfloat16 g_wq2[80 * 192];
__device__ __nv_bfloat16 g_wq3[80 * 128];
__device__ float g_part[8 * 1600 * 80];          // kp2 split-K partials (8 slices)
__device__ float g_G  [8 * 800 * 200];
__device__ float g_LP [8 * 800 * 200];           // log(prior + 1e-8)
__device__ float g_nk [8 * 200];
__device__ float g_zbias[256];

// ========================= inline PTX helpers ==============================

__device__ __forceinline__ uint32_t smem_u32(const void* p) {
    uint32_t a;
    asm("{ .reg .u64 t; cvta.to.shared.u64 t, %1; cvt.u32.u64 %0, t; }"
        : "=r"(a) : "l"(p));
    return a;
}
__device__ __forceinline__ void cp16(uint32_t dst, const void* src, int sz) {
    asm volatile("cp.async.cg.shared.global [%0], [%1], 16, %2;"
                 :: "r"(dst), "l"(src), "r"(sz) : "memory");
}
#define CP_COMMIT() asm volatile("cp.async.commit_group;" ::: "memory")

__device__ __forceinline__ void ldmx4(uint32_t* r, uint32_t addr) {
    asm volatile("ldmatrix.sync.aligned.m8n8.x4.shared.b16 {%0,%1,%2,%3}, [%4];"
                 : "=r"(r[0]), "=r"(r[1]), "=r"(r[2]), "=r"(r[3]) : "r"(addr));
}
__device__ __forceinline__ void ldmx2(uint32_t* r, uint32_t addr) {
    asm volatile("ldmatrix.sync.aligned.m8n8.x2.shared.b16 {%0,%1}, [%2];"
                 : "=r"(r[0]), "=r"(r[1]) : "r"(addr));
}
__device__ __forceinline__ void mma16816(float* c, const uint32_t* a, const uint32_t* bq) {
    asm volatile(
        "mma.sync.aligned.m16n8k16.row.col.f32.bf16.bf16.f32 "
        "{%0,%1,%2,%3}, {%4,%5,%6,%7}, {%8,%9}, {%0,%1,%2,%3};"
        : "+f"(c[0]), "+f"(c[1]), "+f"(c[2]), "+f"(c[3])
        : "r"(a[0]), "r"(a[1]), "r"(a[2]), "r"(a[3]), "r"(bq[0]), "r"(bq[1]));
}

// ============================ prep kernels =================================

__device__ __forceinline__ void wprep_one(const float* W, __nv_bfloat16* Wt,
                                          int idx, int M, int Cin, int Cpad, int taps)
{
    int c = idx % Cpad;
    int r = idx / Cpad;
    int m = r % M;
    int tap = r / M;
    float v = (c < Cin) ? W[((size_t)m * Cin + c) * taps + tap] : 0.f;
    Wt[idx] = __float2bfloat16(v);
}

// kp_w1 (1024,512,3) fp32 -> g_wt [tap][m][c] bf16; smem-staged, coalesced.
// Block handles 1024 flat (m,c) indices = 3072 floats.
__global__ void __launch_bounds__(256) prep_wt_kernel(const float* __restrict__ W,
                                                      __nv_bfloat16* __restrict__ Wt)
{
    __shared__ float s[3072];
    const int base = blockIdx.x * 1024;
    const float4* src = (const float4*)(W + (size_t)base * 3);
    float4* s4 = (float4*)s;
    const int tid = threadIdx.x;
#pragma unroll
    for (int k = 0; k < 3; k++) s4[tid + k * 256] = src[tid + k * 256];
    __syncthreads();
#pragma unroll
    for (int tap = 0; tap < 3; tap++) {
        __nv_bfloat162* dst = (__nv_bfloat162*)(Wt + (size_t)tap * (1024 * 512) + base);
#pragma unroll
        for (int k = 0; k < 2; k++) {
            int p = tid + k * 256;                 // bf16x2 pair index 0..511
            float lo = s[(2 * p) * 3 + tap];
            float hi = s[(2 * p + 1) * 3 + tap];
            dst[p] = __floats2bfloat162_rn(lo, hi);
        }
    }
}

// remaining weights (side stream)
#define WP1 (80 * 1024)
#define WP2 (3 * 160 * 128)
#define WP3 (80 * 192)
#define WP4 (80 * 128)
__global__ void __launch_bounds__(256) prep_wrest_kernel(
    const float* __restrict__ w2, const float* __restrict__ q1,
    const float* __restrict__ q2, const float* __restrict__ q3,
    __nv_bfloat16* __restrict__ o2, __nv_bfloat16* __restrict__ o3,
    __nv_bfloat16* __restrict__ o4, __nv_bfloat16* __restrict__ o5)
{
    int idx = blockIdx.x * 256 + threadIdx.x;
    if (idx < WP1) { wprep_one(w2, o2, idx, 80, 1024, 1024, 1); return; }
    idx -= WP1;
    if (idx < WP2) { wprep_one(q1, o3, idx, 160, 80, 128, 3); return; }
    idx -= WP2;
    if (idx < WP3) { wprep_one(q2, o4, idx, 80, 160, 192, 1); return; }
    idx -= WP3;
    if (idx < WP4) { wprep_one(q3, o5, idx, 80, 80, 128, 1); }
}

// X (B, C, T) fp32 -> guarded [b*(T+1)+1+t][Cpad] bf16 (zero pad cols)
__global__ void __launch_bounds__(256) prep_xpose_kernel(const float* __restrict__ X,
                                                         __nv_bfloat16* __restrict__ Xt,
                                                         int C, int T, int Cpad)
{
    __shared__ float tile[32][33];
    const int b  = blockIdx.z;
    const int t0 = blockIdx.x * 32;
    const int c0 = blockIdx.y * 32;
    const int tx = threadIdx.x, ty = threadIdx.y;
    const float* xb = X + (size_t)b * C * T;
#pragma unroll
    for (int j = 0; j < 32; j += 8) {
        int c = c0 + ty + j, t = t0 + tx;
        tile[ty + j][tx] = (c < C && t < T) ? xb[(size_t)c * T + t] : 0.f;
    }
    __syncthreads();
    __nv_bfloat16* xo = Xt + ((size_t)b * (T + 1) + 1) * Cpad;
#pragma unroll
    for (int j = 0; j < 32; j += 8) {
        int t = t0 + ty + j, c = c0 + tx;
        if (t < T && c < Cpad) xo[(size_t)t * Cpad + c] = __float2bfloat16(tile[tx][ty + j]);
    }
}

// log(prior + 1e-8), vectorized (side stream; hides under kp1)
__global__ void __launch_bounds__(256) prep_logprior_kernel(const float4* __restrict__ P,
                                                            float4* __restrict__ LP)
{
    int i = blockIdx.x * 256 + threadIdx.x;
    if (i >= 8 * 800 * 200 / 4) return;
    float4 p = P[i];
    float4 r;
    r.x = __logf(p.x + 1e-8f);
    r.y = __logf(p.y + 1e-8f);
    r.z = __logf(p.z + 1e-8f);
    r.w = __logf(p.w + 1e-8f);
    LP[i] = r;
}

// fused kp2 split-K(8) reduce + key norms; warp per row (1600 rows)
__global__ void __launch_bounds__(256) reduce_kp2_norms_kernel(
    const float* __restrict__ part, const float* __restrict__ bias,
    __nv_bfloat16* __restrict__ keb, float* __restrict__ nk)
{
    const int lane = threadIdx.x & 31;
    const int row  = blockIdx.x * 8 + (threadIdx.x >> 5);
    float sq = 0.f;
#pragma unroll
    for (int k = 0; k < 3; k++) {
        int m = lane + k * 32;
        if (m < 80) {
            int idx = row * 80 + m;
            float v = bias[m];
#pragma unroll
            for (int s = 0; s < 8; s++) v += part[s * 128000 + idx];
            keb[(size_t)row * 128 + m] = __float2bfloat16(v);
            sq = fmaf(v, v, sq);
        }
    }
#pragma unroll
    for (int o = 16; o > 0; o >>= 1) sq += __shfl_xor_sync(0xffffffffu, sq, o);
    if (lane == 0) nk[row] = sq;
}

// ================= generic time-major conv/GEMM on mma.sync ================
// CTA tile: 128 t x 80 m. 8 warps = 4(t) x 2(m); warp 32t x 40m (2x5 m16n8k16).
// OUT=0 bf16+bias(+relu); OUT=1 fp32+bias; OUT=2 fp32 partial (slice z).
// ZMODE=0: z = batch; ZMODE=1: z = K-slice (merged batch).
// L>0: A rows map i -> i + i/L + 1 (guarded input, 1-tap only).
// Fill descriptors recomputed inline (cheap u32 math) except the TAPS==1
// A path (runtime i/L division) which stays hoisted — relieves reg pressure.

template <int TAPS, bool RELU, int OUT, int ZMODE>
__global__ void __launch_bounds__(256, 2) convmma_kernel(
    const __nv_bfloat16* __restrict__ X, const __nv_bfloat16* __restrict__ W,
    const float* __restrict__ bias, void* __restrict__ Yv,
    int N_t, int Mtot, int Cpad, int nChunks, int wbstride, int ystride, int L)
{
    constexpr int PAD   = (TAPS - 1) / 2;
    constexpr int AROWS = 128 + TAPS - 1;
    constexpr int ABUF  = AROWS * 128;
    constexpr int BROWS = TAPS * 80;
    constexpr int BBUF  = BROWS * 128;
    constexpr int BUF   = ABUF + BBUF + 16;      // +16B trash slot per buffer
    constexpr int nA    = (AROWS * 8 + 255) / 256;
    constexpr int nB    = (BROWS * 8 + 255) / 256;

    extern __shared__ char smem[];
    const uint32_t sbase = smem_u32(smem);
    const int tid  = threadIdx.x;
    const int lane = tid & 31;
    const int wid  = tid >> 5;
    const int t0   = blockIdx.x * 128;
    const int m0   = blockIdx.y * 80;
    const int b    = ZMODE ? 0 : blockIdx.z;
    const int kb   = ZMODE ? blockIdx.z * nChunks : 0;

    const int t_off = (wid & 3) * 32;
    const int m_off = (wid >> 2) * 40;

    const char* xb = (const char*)(X + (size_t)b * N_t * Cpad);
    const char* wb = (const char*)(W + (size_t)b * wbstride);
    const uint32_t cstride = (uint32_t)(Cpad * 2);

    // ---- hoisted A descriptors only for TAPS==1 (runtime division by L) ----
    uint32_t gA[nA], sAo[nA];
    unsigned mA = 0;
    if (TAPS == 1) {
#pragma unroll
        for (int k = 0; k < nA; k++) {
            int idx = tid + k * 256;
            if (idx < AROWS * 8) {
                int row = idx >> 3, seg = idx & 7;
                int t = t0 + row;
                bool ok = t < N_t;
                int i = ok ? t : N_t - 1;
                int xrow = L ? (i + i / L + 1) : i;
                gA[k] = (uint32_t)xrow * cstride + (uint32_t)(seg * 16);
                sAo[k] = row * 128 + ((seg ^ (row & 7)) * 16);
                if (ok) mA |= 1u << k;
            } else {
                gA[k] = 0;
                sAo[k] = ABUF + BBUF;
            }
        }
    }

    float acc[2][5][4];
#pragma unroll
    for (int mt = 0; mt < 2; mt++)
#pragma unroll
        for (int nt = 0; nt < 5; nt++)
#pragma unroll
            for (int r = 0; r < 4; r++) acc[mt][nt][r] = 0.f;

    auto fill = [&](int buf, int chunk) {
        const uint32_t base = sbase + buf * BUF;
        const uint32_t co = (uint32_t)(kb + chunk) * 128u;
        if (TAPS == 3) {
#pragma unroll
            for (int k = 0; k < nA; k++) {
                int idx = tid + k * 256;
                int row = idx >> 3, seg = idx & 7;
                int t = t0 + row - PAD;
                int xrow = t < 0 ? 0 : (t >= N_t ? N_t - 1 : t);
                bool over = idx >= AROWS * 8;
                uint32_t so = over ? (uint32_t)(ABUF + BBUF)
                                   : (uint32_t)(row * 128 + ((seg ^ (row & 7)) * 16));
                cp16(base + so,
                     xb + (uint32_t)xrow * cstride + (uint32_t)(seg * 16) + co,
                     over ? 0 : 16);
            }
        } else {
#pragma unroll
            for (int k = 0; k < nA; k++)
                cp16(base + sAo[k], xb + gA[k] + co, ((mA >> k) & 1) << 4);
        }
#pragma unroll
        for (int k = 0; k < nB; k++) {
            int idx = tid + k * 256;
            int row = idx >> 3, seg = idx & 7;
            int tap = (TAPS == 3) ? (row / 80) : 0;
            int m = m0 + row - tap * 80;
            bool over = idx >= BROWS * 8;
            bool live = !over && (m < Mtot);
            int mc = m < Mtot ? m : Mtot - 1;
            uint32_t so = over ? (uint32_t)(ABUF + BBUF)
                               : (uint32_t)(ABUF + row * 128 + ((seg ^ (row & 7)) * 16));
            cp16(base + so,
                 wb + ((uint32_t)tap * (uint32_t)Mtot + (uint32_t)mc) * cstride
                    + (uint32_t)(seg * 16) + co,
                 live ? 16 : 0);
        }
        CP_COMMIT();
    };

    fill(0, 0);
    const int matm = lane >> 3;
    const int lrow = lane & 7;

    for (int s = 0; s < nChunks; s++) {
        const int cur = s & 1;
        if (s + 1 < nChunks) {
            fill(cur ^ 1, s + 1);
            asm volatile("cp.async.wait_group 1;" ::: "memory");
        } else {
            asm volatile("cp.async.wait_group 0;" ::: "memory");
        }
        __syncthreads();

        const uint32_t aA = sbase + cur * BUF;
        const uint32_t aB = aA + ABUF;
#pragma unroll
        for (int tap = 0; tap < TAPS; tap++) {
#pragma unroll
            for (int ks = 0; ks < 4; ks++) {
                uint32_t afr[2][4];
#pragma unroll
                for (int mt = 0; mt < 2; mt++) {
                    int r = t_off + mt * 16 + (matm & 1) * 8 + lrow + tap;
                    int seg = ks * 2 + (matm >> 1);
                    ldmx4(afr[mt], aA + r * 128 + ((seg ^ (r & 7)) * 16));
                }
                uint32_t bfr[5][2];
#pragma unroll
                for (int np = 0; np < 2; np++) {            // nt pairs via x4
                    int r = tap * 80 + m_off + (2 * np + (matm >> 1)) * 8 + lrow;
                    int seg = ks * 2 + (matm & 1);
                    uint32_t tmp[4];
                    ldmx4(tmp, aB + r * 128 + ((seg ^ (r & 7)) * 16));
                    bfr[2 * np][0] = tmp[0]; bfr[2 * np][1] = tmp[1];
                    bfr[2 * np + 1][0] = tmp[2]; bfr[2 * np + 1][1] = tmp[3];
                }
                {                                            // nt = 4 via x2
                    int r = tap * 80 + m_off + 32 + lrow;
                    int seg = ks * 2 + (matm & 1);
                    ldmx2(bfr[4], aB + r * 128 + ((seg ^ (r & 7)) * 16));
                }
#pragma unroll
                for (int mt = 0; mt < 2; mt++)
#pragma unroll
                    for (int nt = 0; nt < 5; nt++)
                        mma16816(acc[mt][nt], afr[mt], bfr[nt]);
            }
        }
        __syncthreads();
    }

    // epilogue
    const int g = lane >> 2, tg = lane & 3;
#pragma unroll
    for (int mt = 0; mt < 2; mt++) {
#pragma unroll
        for (int half = 0; half < 2; half++) {
            const int t = t0 + t_off + mt * 16 + g + half * 8;
            if (t >= N_t) continue;
#pragma unroll
            for (int nt = 0; nt < 5; nt++) {
                const int m = m0 + m_off + nt * 8 + tg * 2;
                if (m >= Mtot) continue;
                if (OUT == 2) {
                    float2* y = (float2*)((float*)Yv +
                        ((size_t)blockIdx.z * N_t + t) * ystride + m);
                    *y = make_float2(acc[mt][nt][half * 2 + 0], acc[mt][nt][half * 2 + 1]);
                } else {
                    float v0 = acc[mt][nt][half * 2 + 0] + bias[m];
                    float v1 = acc[mt][nt][half * 2 + 1] + bias[m + 1];
                    if (RELU) { v0 = fmaxf(v0, 0.f); v1 = fmaxf(v1, 0.f); }
                    if (OUT == 0) {
                        __nv_bfloat162* y = (__nv_bfloat162*)
                            ((__nv_bfloat16*)Yv + ((size_t)b * N_t + t) * ystride + m);
                        *y = __floats2bfloat162_rn(v0, v1);
                    } else {
                        float2* y = (float2*)
                            ((float*)Yv + ((size_t)b * N_t + t) * ystride + m);
                        *y = make_float2(v0, v1);
                    }
                }
            }
        }
    }
}

// ===================== softmax stage: warp per row =========================
__global__ void __launch_bounds__(256)
attn2_kernel(const float* __restrict__ G, const float* __restrict__ nk,
             const __nv_bfloat16* __restrict__ qeb, const float* __restrict__ LP,
             const unsigned* __restrict__ mask, float* __restrict__ out)
{
    const int lane = threadIdx.x & 31;
    const int row  = blockIdx.x * 8 + (threadIdx.x >> 5);   // b*800+i
    const int b    = row / T1n;

    const __nv_bfloat162* q2 = (const __nv_bfloat162*)(qeb + (size_t)row * 128);
    float nq;
    {
        float2 v = __bfloat1622float2(q2[lane]);
        float s = v.x * v.x + v.y * v.y;
        if (lane < 8) {
            float2 w = __bfloat1622float2(q2[32 + lane]);
            s = fmaf(w.x, w.x, fmaf(w.y, w.y, s));
        }
#pragma unroll
        for (int o = 16; o > 0; o >>= 1) s += __shfl_xor_sync(0xffffffffu, s, o);
        nq = s;
    }

    const float* Grow = G + (size_t)row * T2n;
    const float* nkb  = nk + b * T2n;

    float sc[7];
#pragma unroll
    for (int k = 0; k < 7; k++) {
        int j = lane + k * 32;
        sc[k] = (j < T2n) ? -5e-4f * (nq + nkb[j] - 2.f * Grow[j]) : -1e30f;
    }
    float mx = sc[0];
#pragma unroll
    for (int k = 1; k < 7; k++) mx = fmaxf(mx, sc[k]);
#pragma unroll
    for (int o = 16; o > 0; o >>= 1) mx = fmaxf(mx, __shfl_xor_sync(0xffffffffu, mx, o));
    float se = 0.f;
#pragma unroll
    for (int k = 0; k < 7; k++) se += __expf(sc[k] - mx);
#pragma unroll
    for (int o = 16; o > 0; o >>= 1) se += __shfl_xor_sync(0xffffffffu, se, o);
    const float lse = mx + __logf(se);

    const size_t base = (size_t)row * T2n;
    const float* lrow_p = LP + base;
    float lp[7];
    bool  keep[7];
#pragma unroll
    for (int k = 0; k < 7; k++) {
        int j = lane + k * 32;
        if (j < T2n) {
            lp[k] = sc[k] - lse + lrow_p[j];
            out[(size_t)Bn * T1n * T2n + base + j] = lp[k];
            keep[k] = (mask[b * T2n + j] == 0u);
        } else { lp[k] = -1e30f; keep[k] = false; }
    }

    float m2 = -1e30f;
#pragma unroll
    for (int k = 0; k < 7; k++) if (keep[k]) m2 = fmaxf(m2, lp[k]);
#pragma unroll
    for (int o = 16; o > 0; o >>= 1) m2 = fmaxf(m2, __shfl_xor_sync(0xffffffffu, m2, o));
    float s2 = 0.f;
#pragma unroll
    for (int k = 0; k < 7; k++) if (keep[k]) s2 += __expf(lp[k] - m2);
#pragma unroll
    for (int o = 16; o > 0; o >>= 1) s2 += __shfl_xor_sync(0xffffffffu, s2, o);

#pragma unroll
    for (int k = 0; k < 7; k++) {
        int j = lane + k * 32;
        if (j < T2n)
            out[base + j] = keep[k] ? __expf(lp[k] - m2) / s2 : 0.f;
    }
}

// ---------------------------------------------------------------------------

static void* sym_addr(const void* sym)
{
    void* p = nullptr;
    cudaGetSymbolAddress(&p, sym);
    return p;
}

#define SMEM_T3 (2 * ((130 + 240) * 128 + 16))   // 94752
#define SMEM_T1 (2 * ((128 + 80) * 128 + 16))    // 53280

extern "C" void kernel_launch(void* const* d_in, const int* in_sizes, int n_in,
                              void* d_out, int out_size)
{
    const float*    queries = (const float*)d_in[0];
    const float*    keys    = (const float*)d_in[1];
    const unsigned* mask    = (const unsigned*)d_in[3];
    const float*    prior   = (const float*)d_in[4];
    const float*    kp_w1   = (const float*)d_in[5];
    const float*    kp_b1   = (const float*)d_in[6];
    const float*    kp_w2   = (const float*)d_in[7];
    const float*    kp_b2   = (const float*)d_in[8];
    const float*    qp_w1   = (const float*)d_in[9];
    const float*    qp_b1   = (const float*)d_in[10];
    const float*    qp_w2   = (const float*)d_in[11];
    const float*    qp_b2   = (const float*)d_in[12];
    const float*    qp_w3   = (const float*)d_in[13];
    const float*    qp_b3   = (const float*)d_in[14];
    float* out = (float*)d_out;

    __nv_bfloat16* xt  = (__nv_bfloat16*)sym_addr(g_xt);
    __nv_bfloat16* xq  = (__nv_bfloat16*)sym_addr(g_xq);
    __nv_bfloat16* h1  = (__nv_bfloat16*)sym_addr(g_h1);
    __nv_bfloat16* keb = (__nv_bfloat16*)sym_addr(g_keb);
    __nv_bfloat16* hq1 = (__nv_bfloat16*)sym_addr(g_hq1);
    __nv_bfloat16* hq2 = (__nv_bfloat16*)sym_addr(g_hq2);
    __nv_bfloat16* qeb = (__nv_bfloat16*)sym_addr(g_qeb);
    __nv_bfloat16* wt  = (__nv_bfloat16*)sym_addr(g_wt);
    __nv_bfloat16* wk2 = (__nv_bfloat16*)sym_addr(g_wk2);
    __nv_bfloat16* wq1 = (__nv_bfloat16*)sym_addr(g_wq1);
    __nv_bfloat16* wq2 = (__nv_bfloat16*)sym_addr(g_wq2);
    __nv_bfloat16* wq3 = (__nv_bfloat16*)sym_addr(g_wq3);
    float* part = (float*)sym_addr(g_part);
    float* G    = (float*)sym_addr(g_G);
    float* LP   = (float*)sym_addr(g_LP);
    float* nk   = (float*)sym_addr(g_nk);
    float* zb   = (float*)sym_addr(g_zbias);

    static cudaStream_t s1, s2;
    static cudaEvent_t evRoot, evQ, evK;
    static bool init_done = false;
    if (!init_done) {
        cudaStreamCreateWithFlags(&s1, cudaStreamNonBlocking);
        cudaStreamCreateWithFlags(&s2, cudaStreamNonBlocking);
        cudaEventCreateWithFlags(&evRoot, cudaEventDisableTiming);
        cudaEventCreateWithFlags(&evQ, cudaEventDisableTiming);
        cudaEventCreateWithFlags(&evK, cudaEventDisableTiming);
        cudaFuncSetAttribute(convmma_kernel<3, true, 0, 0>,
                             cudaFuncAttributeMaxDynamicSharedMemorySize, SMEM_T3);
        cudaFuncSetAttribute(convmma_kernel<1, true, 0, 0>,
                             cudaFuncAttributeMaxDynamicSharedMemorySize, SMEM_T1);
        cudaFuncSetAttribute(convmma_kernel<1, false, 0, 0>,
                             cudaFuncAttributeMaxDynamicSharedMemorySize, SMEM_T1);
        cudaFuncSetAttribute(convmma_kernel<1, false, 1, 0>,
                             cudaFuncAttributeMaxDynamicSharedMemorySize, SMEM_T1);
        cudaFuncSetAttribute(convmma_kernel<1, false, 2, 1>,
                             cudaFuncAttributeMaxDynamicSharedMemorySize, SMEM_T1);
        init_done = true;
    }

    // ---- fork both side streams off the origin stream ----
    cudaEventRecord(evRoot, 0);
    cudaStreamWaitEvent(s1, evRoot, 0);
    cudaStreamWaitEvent(s2, evRoot, 0);

    // ---- s2: key transpose (parallel with prep_wt) ----
    prep_xpose_kernel<<<dim3(7, 16, 8), dim3(32, 8), 0, s2>>>(keys, xt, 512, T2n, 512);
    cudaEventRecord(evK, s2);

    // ---- s1: query side (hidden under key chain) ----
    prep_wrest_kernel<<<(WP1 + WP2 + WP3 + WP4 + 255) / 256, 256, 0, s1>>>(
        kp_w2, qp_w1, qp_w2, qp_w3, wk2, wq1, wq2, wq3);
    prep_xpose_kernel<<<dim3(25, 4, 8), dim3(32, 8), 0, s1>>>(queries, xq, 80, T1n, 128);
    convmma_kernel<3, true, 0, 0><<<dim3(51, 2, 1), 256, SMEM_T3, s1>>>(
        xq, wq1, qp_b1, hq1, 6409, 160, 128, 2, 0, 192, 0);
    convmma_kernel<1, true, 0, 0><<<dim3(50, 1, 1), 256, SMEM_T1, s1>>>(
        hq1, wq2, qp_b2, hq2, 6400, 80, 192, 3, 0, 128, 800);
    convmma_kernel<1, false, 0, 0><<<dim3(50, 1, 1), 256, SMEM_T1, s1>>>(
        hq2, wq3, qp_b3, qeb, 6400, 80, 128, 2, 0, 128, 0);
    prep_logprior_kernel<<<(8 * 800 * 200 / 4 + 255) / 256, 256, 0, s1>>>(
        (const float4*)prior, (float4*)LP);
    cudaEventRecord(evQ, s1);

    // ---- stream 0: key chain (critical path) ----
    prep_wt_kernel<<<512, 256>>>(kp_w1, wt);
    cudaStreamWaitEvent(0, evK, 0);
    convmma_kernel<3, true, 0, 0><<<dim3(13, 13, 1), 256, SMEM_T3>>>(
        xt, wt, kp_b1, h1, 1609, 1024, 512, 8, 0, 1024, 0);
    convmma_kernel<1, false, 2, 1><<<dim3(13, 1, 8), 256, SMEM_T1>>>(
        h1, wk2, zb, part, 1600, 80, 1024, 2, 0, 80, 200);
    reduce_kp2_norms_kernel<<<200, 256>>>(part, kp_b2, keb, nk);

    // ---- join, then Gram + softmax ----
    cudaStreamWaitEvent(0, evQ, 0);
    convmma_kernel<1, false, 1, 0><<<dim3(7, 3, 8), 256, SMEM_T1>>>(
        qeb, keb, zb, G, 800, 200, 128, 2, 200 * 128, 200, 0);
    attn2_kernel<<<800, 256>>>(G, nk, qeb, LP, mask, out);
}

// round 16
// speedup vs baseline: 1.0384x; 1.0384x over previous
#include <cuda_runtime.h>
#include <cuda_bf16.h>
#include <cstdint>

// ---------------------------------------------------------------------------
// ConvAttention, R15: kp1 split-K x2 (fp32 partials + fused reduce/relu/bias),
// 3-stream DAG. R14 with the KP1_SLICE stride bug fixed (1609*1024, matching
// the convmma OUT=2 epilogue's z * N_t * ystride).
// ---------------------------------------------------------------------------

#define Bn   8
#define T1n  800
#define T2n  200

// -------- scratch (device globals; zero-initialized, guards never written) --
__device__ __nv_bfloat16 g_xt [1664 * 512];      // keys guarded [1609+pad][512]
__device__ __nv_bfloat16 g_xq [6528 * 128];      // queries guarded [6409+pad][128]
__device__ __nv_bfloat16 g_h1 [1664 * 1024];     // kp1 out, guard layout
__device__ __nv_bfloat16 g_keb[1600 * 128];      // key emb plain (pads stay 0)
__device__ __nv_bfloat16 g_hq1[6528 * 192];      // qp1 out, guard layout
__device__ __nv_bfloat16 g_hq2[6400 * 128];      // qp2 out plain
__device__ __nv_bfloat16 g_qeb[6400 * 128];      // query emb plain
__device__ __nv_bfloat16 g_wt [3 * 1024 * 512];  // kp_w1 [tap][m][512]
__device__ __nv_bfloat16 g_wk2[80 * 1024];
__device__ __nv_bfloat16 g_wq1[3 * 160 * 128];
__device__ __nv_bfloat16 g_wq2[80 * 192];
__device__ __nv_bfloat16 g_wq3[80 * 128];
__device__ float g_part[2 * 1664 * 1024];        // kp1 splitK partials; reused by kp2
__device__ float g_G  [8 * 800 * 200];
__device__ float g_LP [8 * 800 * 200];           // log(prior + 1e-8)
__device__ float g_nk [8 * 200];
__device__ float g_zbias[256];

#define KP1_SLICE (1609 * 1024)  // fp32 elems per kp1 K-slice == z*N_t*ystride stride

// ========================= inline PTX helpers ==============================

__device__ __forceinline__ uint32_t smem_u32(const void* p) {
    uint32_t a;
    asm("{ .reg .u64 t; cvta.to.shared.u64 t, %1; cvt.u32.u64 %0, t; }"
        : "=r"(a) : "l"(p));
    return a;
}
__device__ __forceinline__ void cp16(uint32_t dst, const void* src, int sz) {
    asm volatile("cp.async.cg.shared.global [%0], [%1], 16, %2;"
                 :: "r"(dst), "l"(src), "r"(sz) : "memory");
}
#define CP_COMMIT() asm volatile("cp.async.commit_group;" ::: "memory")

__device__ __forceinline__ void ldmx4(uint32_t* r, uint32_t addr) {
    asm volatile("ldmatrix.sync.aligned.m8n8.x4.shared.b16 {%0,%1,%2,%3}, [%4];"
                 : "=r"(r[0]), "=r"(r[1]), "=r"(r[2]), "=r"(r[3]) : "r"(addr));
}
__device__ __forceinline__ void ldmx2(uint32_t* r, uint32_t addr) {
    asm volatile("ldmatrix.sync.aligned.m8n8.x2.shared.b16 {%0,%1}, [%2];"
                 : "=r"(r[0]), "=r"(r[1]) : "r"(addr));
}
__device__ __forceinline__ void mma16816(float* c, const uint32_t* a, const uint32_t* bq) {
    asm volatile(
        "mma.sync.aligned.m16n8k16.row.col.f32.bf16.bf16.f32 "
        "{%0,%1,%2,%3}, {%4,%5,%6,%7}, {%8,%9}, {%0,%1,%2,%3};"
        : "+f"(c[0]), "+f"(c[1]), "+f"(c[2]), "+f"(c[3])
        : "r"(a[0]), "r"(a[1]), "r"(a[2]), "r"(a[3]), "r"(bq[0]), "r"(bq[1]));
}

__device__ __forceinline__ uint32_t bf2_to_u32(__nv_bfloat162 v) {
    union { __nv_bfloat162 h; uint32_t u; } cvt;
    cvt.h = v;
    return cvt.u;
}

// ============================ prep kernels =================================

__device__ __forceinline__ void wprep_one(const float* W, __nv_bfloat16* Wt,
                                          int idx, int M, int Cin, int Cpad, int taps)
{
    int c = idx % Cpad;
    int r = idx / Cpad;
    int m = r % M;
    int tap = r / M;
    float v = (c < Cin) ? W[((size_t)m * Cin + c) * taps + tap] : 0.f;
    Wt[idx] = __float2bfloat16(v);
}

// kp_w1 (1024,512,3) fp32 -> g_wt [tap][m][c] bf16; smem-staged, coalesced.
__global__ void __launch_bounds__(256) prep_wt_kernel(const float* __restrict__ W,
                                                      __nv_bfloat16* __restrict__ Wt)
{
    __shared__ float s[3072];
    const int base = blockIdx.x * 1024;
    const float4* src = (const float4*)(W + (size_t)base * 3);
    float4* s4 = (float4*)s;
    const int tid = threadIdx.x;
#pragma unroll
    for (int k = 0; k < 3; k++) s4[tid + k * 256] = src[tid + k * 256];
    __syncthreads();
#pragma unroll
    for (int tap = 0; tap < 3; tap++) {
        __nv_bfloat162* dst = (__nv_bfloat162*)(Wt + (size_t)tap * (1024 * 512) + base);
#pragma unroll
        for (int k = 0; k < 2; k++) {
            int p = tid + k * 256;
            float lo = s[(2 * p) * 3 + tap];
            float hi = s[(2 * p + 1) * 3 + tap];
            dst[p] = __floats2bfloat162_rn(lo, hi);
        }
    }
}

// remaining weights (side stream)
#define WP1 (80 * 1024)
#define WP2 (3 * 160 * 128)
#define WP3 (80 * 192)
#define WP4 (80 * 128)
__global__ void __launch_bounds__(256) prep_wrest_kernel(
    const float* __restrict__ w2, const float* __restrict__ q1,
    const float* __restrict__ q2, const float* __restrict__ q3,
    __nv_bfloat16* __restrict__ o2, __nv_bfloat16* __restrict__ o3,
    __nv_bfloat16* __restrict__ o4, __nv_bfloat16* __restrict__ o5)
{
    int idx = blockIdx.x * 256 + threadIdx.x;
    if (idx < WP1) { wprep_one(w2, o2, idx, 80, 1024, 1024, 1); return; }
    idx -= WP1;
    if (idx < WP2) { wprep_one(q1, o3, idx, 160, 80, 128, 3); return; }
    idx -= WP2;
    if (idx < WP3) { wprep_one(q2, o4, idx, 80, 160, 192, 1); return; }
    idx -= WP3;
    if (idx < WP4) { wprep_one(q3, o5, idx, 80, 80, 128, 1); }
}

// X (B, C, T) fp32 -> guarded [b*(T+1)+1+t][Cpad] bf16 (zero pad cols)
__global__ void __launch_bounds__(256) prep_xpose_kernel(const float* __restrict__ X,
                                                         __nv_bfloat16* __restrict__ Xt,
                                                         int C, int T, int Cpad)
{
    __shared__ float tile[32][33];
    const int b  = blockIdx.z;
    const int t0 = blockIdx.x * 32;
    const int c0 = blockIdx.y * 32;
    const int tx = threadIdx.x, ty = threadIdx.y;
    const float* xb = X + (size_t)b * C * T;
#pragma unroll
    for (int j = 0; j < 32; j += 8) {
        int c = c0 + ty + j, t = t0 + tx;
        tile[ty + j][tx] = (c < C && t < T) ? xb[(size_t)c * T + t] : 0.f;
    }
    __syncthreads();
    __nv_bfloat16* xo = Xt + ((size_t)b * (T + 1) + 1) * Cpad;
#pragma unroll
    for (int j = 0; j < 32; j += 8) {
        int t = t0 + ty + j, c = c0 + tx;
        if (t < T && c < Cpad) xo[(size_t)t * Cpad + c] = __float2bfloat16(tile[tx][ty + j]);
    }
}

// log(prior + 1e-8), vectorized (side stream; hides under kp1)
__global__ void __launch_bounds__(256) prep_logprior_kernel(const float4* __restrict__ P,
                                                            float4* __restrict__ LP)
{
    int i = blockIdx.x * 256 + threadIdx.x;
    if (i >= 8 * 800 * 200 / 4) return;
    float4 p = P[i];
    float4 r;
    r.x = __logf(p.x + 1e-8f);
    r.y = __logf(p.y + 1e-8f);
    r.z = __logf(p.z + 1e-8f);
    r.w = __logf(p.w + 1e-8f);
    LP[i] = r;
}

// kp1 split-K(2) reduce + bias + ReLU -> bf16 h1 (guard layout, valid rows only)
// 1600 valid rows x 1024 ch; thread = 4 consecutive channels.
__global__ void __launch_bounds__(256) reduce_kp1_kernel(
    const float* __restrict__ part, const float* __restrict__ bias,
    __nv_bfloat16* __restrict__ h1)
{
    int idx = blockIdx.x * 256 + threadIdx.x;      // 1600*256 total
    int row = idx >> 8;
    int ms  = (idx & 255) * 4;
    int r   = row + row / 200 + 1;                 // guarded row
    const float4 p0 = *(const float4*)(part + (size_t)r * 1024 + ms);
    const float4 p1 = *(const float4*)(part + (size_t)KP1_SLICE + (size_t)r * 1024 + ms);
    float v0 = fmaxf(p0.x + p1.x + bias[ms + 0], 0.f);
    float v1 = fmaxf(p0.y + p1.y + bias[ms + 1], 0.f);
    float v2 = fmaxf(p0.z + p1.z + bias[ms + 2], 0.f);
    float v3 = fmaxf(p0.w + p1.w + bias[ms + 3], 0.f);
    uint2 o;
    o.x = bf2_to_u32(__floats2bfloat162_rn(v0, v1));
    o.y = bf2_to_u32(__floats2bfloat162_rn(v2, v3));
    *(uint2*)(h1 + (size_t)r * 1024 + ms) = o;
}

// fused kp2 split-K(8) reduce + key norms; warp per row (1600 rows)
__global__ void __launch_bounds__(256) reduce_kp2_norms_kernel(
    const float* __restrict__ part, const float* __restrict__ bias,
    __nv_bfloat16* __restrict__ keb, float* __restrict__ nk)
{
    const int lane = threadIdx.x & 31;
    const int row  = blockIdx.x * 8 + (threadIdx.x >> 5);
    float sq = 0.f;
#pragma unroll
    for (int k = 0; k < 3; k++) {
        int m = lane + k * 32;
        if (m < 80) {
            int idx = row * 80 + m;
            float v = bias[m];
#pragma unroll
            for (int s = 0; s < 8; s++) v += part[s * 128000 + idx];
            keb[(size_t)row * 128 + m] = __float2bfloat16(v);
            sq = fmaf(v, v, sq);
        }
    }
#pragma unroll
    for (int o = 16; o > 0; o >>= 1) sq += __shfl_xor_sync(0xffffffffu, sq, o);
    if (lane == 0) nk[row] = sq;
}

// ================= generic time-major conv/GEMM on mma.sync ================
// CTA tile: 128 t x 80 m. 8 warps = 4(t) x 2(m); warp 32t x 40m (2x5 m16n8k16).
// OUT=0 bf16+bias(+relu); OUT=1 fp32+bias; OUT=2 fp32 partial (slice z).
// ZMODE=0: z = batch; ZMODE=1: z = K-slice (merged batch).
// L>0: A rows map i -> i + i/L + 1 (guarded input, 1-tap only).

template <int TAPS, bool RELU, int OUT, int ZMODE>
__global__ void __launch_bounds__(256, 2) convmma_kernel(
    const __nv_bfloat16* __restrict__ X, const __nv_bfloat16* __restrict__ W,
    const float* __restrict__ bias, void* __restrict__ Yv,
    int N_t, int Mtot, int Cpad, int nChunks, int wbstride, int ystride, int L)
{
    constexpr int PAD   = (TAPS - 1) / 2;
    constexpr int AROWS = 128 + TAPS - 1;
    constexpr int ABUF  = AROWS * 128;
    constexpr int BROWS = TAPS * 80;
    constexpr int BBUF  = BROWS * 128;
    constexpr int BUF   = ABUF + BBUF + 16;      // +16B trash slot per buffer
    constexpr int nA    = (AROWS * 8 + 255) / 256;
    constexpr int nB    = (BROWS * 8 + 255) / 256;

    extern __shared__ char smem[];
    const uint32_t sbase = smem_u32(smem);
    const int tid  = threadIdx.x;
    const int lane = tid & 31;
    const int wid  = tid >> 5;
    const int t0   = blockIdx.x * 128;
    const int m0   = blockIdx.y * 80;
    const int b    = ZMODE ? 0 : blockIdx.z;
    const int kb   = ZMODE ? blockIdx.z * nChunks : 0;

    const int t_off = (wid & 3) * 32;
    const int m_off = (wid >> 2) * 40;

    const char* xb = (const char*)(X + (size_t)b * N_t * Cpad);
    const char* wb = (const char*)(W + (size_t)b * wbstride);
    const uint32_t cstride = (uint32_t)(Cpad * 2);

    // ---- hoisted A descriptors only for TAPS==1 (runtime division by L) ----
    uint32_t gA[nA], sAo[nA];
    unsigned mA = 0;
    if (TAPS == 1) {
#pragma unroll
        for (int k = 0; k < nA; k++) {
            int idx = tid + k * 256;
            if (idx < AROWS * 8) {
                int row = idx >> 3, seg = idx & 7;
                int t = t0 + row;
                bool ok = t < N_t;
                int i = ok ? t : N_t - 1;
                int xrow = L ? (i + i / L + 1) : i;
                gA[k] = (uint32_t)xrow * cstride + (uint32_t)(seg * 16);
                sAo[k] = row * 128 + ((seg ^ (row & 7)) * 16);
                if (ok) mA |= 1u << k;
            } else {
                gA[k] = 0;
                sAo[k] = ABUF + BBUF;
            }
        }
    }

    float acc[2][5][4];
#pragma unroll
    for (int mt = 0; mt < 2; mt++)
#pragma unroll
        for (int nt = 0; nt < 5; nt++)
#pragma unroll
            for (int r = 0; r < 4; r++) acc[mt][nt][r] = 0.f;

    auto fill = [&](int buf, int chunk) {
        const uint32_t base = sbase + buf * BUF;
        const uint32_t co = (uint32_t)(kb + chunk) * 128u;
        if (TAPS == 3) {
#pragma unroll
            for (int k = 0; k < nA; k++) {
                int idx = tid + k * 256;
                int row = idx >> 3, seg = idx & 7;
                int t = t0 + row - PAD;
                int xrow = t < 0 ? 0 : (t >= N_t ? N_t - 1 : t);
                bool over = idx >= AROWS * 8;
                uint32_t so = over ? (uint32_t)(ABUF + BBUF)
                                   : (uint32_t)(row * 128 + ((seg ^ (row & 7)) * 16));
                cp16(base + so,
                     xb + (uint32_t)xrow * cstride + (uint32_t)(seg * 16) + co,
                     over ? 0 : 16);
            }
        } else {
#pragma unroll
            for (int k = 0; k < nA; k++)
                cp16(base + sAo[k], xb + gA[k] + co, ((mA >> k) & 1) << 4);
        }
#pragma unroll
        for (int k = 0; k < nB; k++) {
            int idx = tid + k * 256;
            int row = idx >> 3, seg = idx & 7;
            int tap = (TAPS == 3) ? (row / 80) : 0;
            int m = m0 + row - tap * 80;
            bool over = idx >= BROWS * 8;
            bool live = !over && (m < Mtot);
            int mc = m < Mtot ? m : Mtot - 1;
            uint32_t so = over ? (uint32_t)(ABUF + BBUF)
                               : (uint32_t)(ABUF + row * 128 + ((seg ^ (row & 7)) * 16));
            cp16(base + so,
                 wb + ((uint32_t)tap * (uint32_t)Mtot + (uint32_t)mc) * cstride
                    + (uint32_t)(seg * 16) + co,
                 live ? 16 : 0);
        }
        CP_COMMIT();
    };

    fill(0, 0);
    const int matm = lane >> 3;
    const int lrow = lane & 7;

    for (int s = 0; s < nChunks; s++) {
        const int cur = s & 1;
        if (s + 1 < nChunks) {
            fill(cur ^ 1, s + 1);
            asm volatile("cp.async.wait_group 1;" ::: "memory");
        } else {
            asm volatile("cp.async.wait_group 0;" ::: "memory");
        }
        __syncthreads();

        const uint32_t aA = sbase + cur * BUF;
        const uint32_t aB = aA + ABUF;
#pragma unroll
        for (int tap = 0; tap < TAPS; tap++) {
#pragma unroll
            for (int ks = 0; ks < 4; ks++) {
                uint32_t afr[2][4];
#pragma unroll
                for (int mt = 0; mt < 2; mt++) {
                    int r = t_off + mt * 16 + (matm & 1) * 8 + lrow + tap;
                    int seg = ks * 2 + (matm >> 1);
                    ldmx4(afr[mt], aA + r * 128 + ((seg ^ (r & 7)) * 16));
                }
                uint32_t bfr[5][2];
#pragma unroll
                for (int np = 0; np < 2; np++) {            // nt pairs via x4
                    int r = tap * 80 + m_off + (2 * np + (matm >> 1)) * 8 + lrow;
                    int seg = ks * 2 + (matm & 1);
                    uint32_t tmp[4];
                    ldmx4(tmp, aB + r * 128 + ((seg ^ (r & 7)) * 16));
                    bfr[2 * np][0] = tmp[0]; bfr[2 * np][1] = tmp[1];
                    bfr[2 * np + 1][0] = tmp[2]; bfr[2 * np + 1][1] = tmp[3];
                }
                {                                            // nt = 4 via x2
                    int r = tap * 80 + m_off + 32 + lrow;
                    int seg = ks * 2 + (matm & 1);
                    ldmx2(bfr[4], aB + r * 128 + ((seg ^ (r & 7)) * 16));
                }
#pragma unroll
                for (int mt = 0; mt < 2; mt++)
#pragma unroll
                    for (int nt = 0; nt < 5; nt++)
                        mma16816(acc[mt][nt], afr[mt], bfr[nt]);
            }
        }
        __syncthreads();
    }

    // epilogue
    const int g = lane >> 2, tg = lane & 3;
#pragma unroll
    for (int mt = 0; mt < 2; mt++) {
#pragma unroll
        for (int half = 0; half < 2; half++) {
            const int t = t0 + t_off + mt * 16 + g + half * 8;
            if (t >= N_t) continue;
#pragma unroll
            for (int nt = 0; nt < 5; nt++) {
                const int m = m0 + m_off + nt * 8 + tg * 2;
                if (m >= Mtot) continue;
                if (OUT == 2) {
                    float2* y = (float2*)((float*)Yv +
                        ((size_t)blockIdx.z * N_t + t) * ystride + m);
                    *y = make_float2(acc[mt][nt][half * 2 + 0], acc[mt][nt][half * 2 + 1]);
                } else {
                    float v0 = acc[mt][nt][half * 2 + 0] + bias[m];
                    float v1 = acc[mt][nt][half * 2 + 1] + bias[m + 1];
                    if (RELU) { v0 = fmaxf(v0, 0.f); v1 = fmaxf(v1, 0.f); }
                    if (OUT == 0) {
                        __nv_bfloat162* y = (__nv_bfloat162*)
                            ((__nv_bfloat16*)Yv + ((size_t)b * N_t + t) * ystride + m);
                        *y = __floats2bfloat162_rn(v0, v1);
                    } else {
                        float2* y = (float2*)
                            ((float*)Yv + ((size_t)b * N_t + t) * ystride + m);
                        *y = make_float2(v0, v1);
                    }
                }
            }
        }
    }
}

// ===================== softmax stage: warp per row =========================
__global__ void __launch_bounds__(256)
attn2_kernel(const float* __restrict__ G, const float* __restrict__ nk,
             const __nv_bfloat16* __restrict__ qeb, const float* __restrict__ LP,
             const unsigned* __restrict__ mask, float* __restrict__ out)
{
    const int lane = threadIdx.x & 31;
    const int row  = blockIdx.x * 8 + (threadIdx.x >> 5);   // b*800+i
    const int b    = row / T1n;

    const __nv_bfloat162* q2 = (const __nv_bfloat162*)(qeb + (size_t)row * 128);
    float nq;
    {
        float2 v = __bfloat1622float2(q2[lane]);
        float s = v.x * v.x + v.y * v.y;
        if (lane < 8) {
            float2 w = __bfloat1622float2(q2[32 + lane]);
            s = fmaf(w.x, w.x, fmaf(w.y, w.y, s));
        }
#pragma unroll
        for (int o = 16; o > 0; o >>= 1) s += __shfl_xor_sync(0xffffffffu, s, o);
        nq = s;
    }

    const float* Grow = G + (size_t)row * T2n;
    const float* nkb  = nk + b * T2n;

    float sc[7];
#pragma unroll
    for (int k = 0; k < 7; k++) {
        int j = lane + k * 32;
        sc[k] = (j < T2n) ? -5e-4f * (nq + nkb[j] - 2.f * Grow[j]) : -1e30f;
    }
    float mx = sc[0];
#pragma unroll
    for (int k = 1; k < 7; k++) mx = fmaxf(mx, sc[k]);
#pragma unroll
    for (int o = 16; o > 0; o >>= 1) mx = fmaxf(mx, __shfl_xor_sync(0xffffffffu, mx, o));
    float se = 0.f;
#pragma unroll
    for (int k = 0; k < 7; k++) se += __expf(sc[k] - mx);
#pragma unroll
    for (int o = 16; o > 0; o >>= 1) se += __shfl_xor_sync(0xffffffffu, se, o);
    const float lse = mx + __logf(se);

    const size_t base = (size_t)row * T2n;
    const float* lrow_p = LP + base;
    float lp[7];
    bool  keep[7];
#pragma unroll
    for (int k = 0; k < 7; k++) {
        int j = lane + k * 32;
        if (j < T2n) {
            lp[k] = sc[k] - lse + lrow_p[j];
            out[(size_t)Bn * T1n * T2n + base + j] = lp[k];
            keep[k] = (mask[b * T2n + j] == 0u);
        } else { lp[k] = -1e30f; keep[k] = false; }
    }

    float m2 = -1e30f;
#pragma unroll
    for (int k = 0; k < 7; k++) if (keep[k]) m2 = fmaxf(m2, lp[k]);
#pragma unroll
    for (int o = 16; o > 0; o >>= 1) m2 = fmaxf(m2, __shfl_xor_sync(0xffffffffu, m2, o));
    float s2 = 0.f;
#pragma unroll
    for (int k = 0; k < 7; k++) if (keep[k]) s2 += __expf(lp[k] - m2);
#pragma unroll
    for (int o = 16; o > 0; o >>= 1) s2 += __shfl_xor_sync(0xffffffffu, s2, o);

#pragma unroll
    for (int k = 0; k < 7; k++) {
        int j = lane + k * 32;
        if (j < T2n)
            out[base + j] = keep[k] ? __expf(lp[k] - m2) / s2 : 0.f;
    }
}

// ---------------------------------------------------------------------------

static void* sym_addr(const void* sym)
{
    void* p = nullptr;
    cudaGetSymbolAddress(&p, sym);
    return p;
}

#define SMEM_T3 (2 * ((130 + 240) * 128 + 16))   // 94752
#define SMEM_T1 (2 * ((128 + 80) * 128 + 16))    // 53280

extern "C" void kernel_launch(void* const* d_in, const int* in_sizes, int n_in,
                              void* d_out, int out_size)
{
    const float*    queries = (const float*)d_in[0];
    const float*    keys    = (const float*)d_in[1];
    const unsigned* mask    = (const unsigned*)d_in[3];
    const float*    prior   = (const float*)d_in[4];
    const float*    kp_w1   = (const float*)d_in[5];
    const float*    kp_b1   = (const float*)d_in[6];
    const float*    kp_w2   = (const float*)d_in[7];
    const float*    kp_b2   = (const float*)d_in[8];
    const float*    qp_w1   = (const float*)d_in[9];
    const float*    qp_b1   = (const float*)d_in[10];
    const float*    qp_w2   = (const float*)d_in[11];
    const float*    qp_b2   = (const float*)d_in[12];
    const float*    qp_w3   = (const float*)d_in[13];
    const float*    qp_b3   = (const float*)d_in[14];
    float* out = (float*)d_out;

    __nv_bfloat16* xt  = (__nv_bfloat16*)sym_addr(g_xt);
    __nv_bfloat16* xq  = (__nv_bfloat16*)sym_addr(g_xq);
    __nv_bfloat16* h1  = (__nv_bfloat16*)sym_addr(g_h1);
    __nv_bfloat16* keb = (__nv_bfloat16*)sym_addr(g_keb);
    __nv_bfloat16* hq1 = (__nv_bfloat16*)sym_addr(g_hq1);
    __nv_bfloat16* hq2 = (__nv_bfloat16*)sym_addr(g_hq2);
    __nv_bfloat16* qeb = (__nv_bfloat16*)sym_addr(g_qeb);
    __nv_bfloat16* wt  = (__nv_bfloat16*)sym_addr(g_wt);
    __nv_bfloat16* wk2 = (__nv_bfloat16*)sym_addr(g_wk2);
    __nv_bfloat16* wq1 = (__nv_bfloat16*)sym_addr(g_wq1);
    __nv_bfloat16* wq2 = (__nv_bfloat16*)sym_addr(g_wq2);
    __nv_bfloat16* wq3 = (__nv_bfloat16*)sym_addr(g_wq3);
    float* part = (float*)sym_addr(g_part);
    float* G    = (float*)sym_addr(g_G);
    float* LP   = (float*)sym_addr(g_LP);
    float* nk   = (float*)sym_addr(g_nk);
    float* zb   = (float*)sym_addr(g_zbias);

    static cudaStream_t s1, s2;
    static cudaEvent_t evRoot, evQ, evK;
    static bool init_done = false;
    if (!init_done) {
        cudaStreamCreateWithFlags(&s1, cudaStreamNonBlocking);
        cudaStreamCreateWithFlags(&s2, cudaStreamNonBlocking);
        cudaEventCreateWithFlags(&evRoot, cudaEventDisableTiming);
        cudaEventCreateWithFlags(&evQ, cudaEventDisableTiming);
        cudaEventCreateWithFlags(&evK, cudaEventDisableTiming);
        cudaFuncSetAttribute(convmma_kernel<3, true, 0, 0>,
                             cudaFuncAttributeMaxDynamicSharedMemorySize, SMEM_T3);
        cudaFuncSetAttribute(convmma_kernel<3, false, 2, 1>,
                             cudaFuncAttributeMaxDynamicSharedMemorySize, SMEM_T3);
        cudaFuncSetAttribute(convmma_kernel<1, true, 0, 0>,
                             cudaFuncAttributeMaxDynamicSharedMemorySize, SMEM_T1);
        cudaFuncSetAttribute(convmma_kernel<1, false, 0, 0>,
                             cudaFuncAttributeMaxDynamicSharedMemorySize, SMEM_T1);
        cudaFuncSetAttribute(convmma_kernel<1, false, 1, 0>,
                             cudaFuncAttributeMaxDynamicSharedMemorySize, SMEM_T1);
        cudaFuncSetAttribute(convmma_kernel<1, false, 2, 1>,
                             cudaFuncAttributeMaxDynamicSharedMemorySize, SMEM_T1);
        init_done = true;
    }

    // ---- fork both side streams off the origin stream ----
    cudaEventRecord(evRoot, 0);
    cudaStreamWaitEvent(s1, evRoot, 0);
    cudaStreamWaitEvent(s2, evRoot, 0);

    // ---- s2: key transpose (parallel with prep_wt) ----
    prep_xpose_kernel<<<dim3(7, 16, 8), dim3(32, 8), 0, s2>>>(keys, xt, 512, T2n, 512);
    cudaEventRecord(evK, s2);

    // ---- s1: query side (hidden under key chain) ----
    prep_wrest_kernel<<<(WP1 + WP2 + WP3 + WP4 + 255) / 256, 256, 0, s1>>>(
        kp_w2, qp_w1, qp_w2, qp_w3, wk2, wq1, wq2, wq3);
    prep_xpose_kernel<<<dim3(25, 4, 8), dim3(32, 8), 0, s1>>>(queries, xq, 80, T1n, 128);
    convmma_kernel<3, true, 0, 0><<<dim3(51, 2, 1), 256, SMEM_T3, s1>>>(
        xq, wq1, qp_b1, hq1, 6409, 160, 128, 2, 0, 192, 0);
    convmma_kernel<1, true, 0, 0><<<dim3(50, 1, 1), 256, SMEM_T1, s1>>>(
        hq1, wq2, qp_b2, hq2, 6400, 80, 192, 3, 0, 128, 800);
    convmma_kernel<1, false, 0, 0><<<dim3(50, 1, 1), 256, SMEM_T1, s1>>>(
        hq2, wq3, qp_b3, qeb, 6400, 80, 128, 2, 0, 128, 0);
    prep_logprior_kernel<<<(8 * 800 * 200 / 4 + 255) / 256, 256, 0, s1>>>(
        (const float4*)prior, (float4*)LP);
    cudaEventRecord(evQ, s1);

    // ---- stream 0: key chain (critical path) ----
    prep_wt_kernel<<<512, 256>>>(kp_w1, wt);
    cudaStreamWaitEvent(0, evK, 0);
    // kp1 split-K x2: fp32 partials (slice stride = N_t*ystride = 1609*1024),
    // then fused reduce+bias+ReLU -> bf16 h1
    convmma_kernel<3, false, 2, 1><<<dim3(13, 13, 2), 256, SMEM_T3>>>(
        xt, wt, zb, part, 1609, 1024, 512, 4, 0, 1024, 0);
    reduce_kp1_kernel<<<1600, 256>>>(part, kp_b1, h1);
    // kp2: 1024->80, merged valid rows, rowmap L=200, split-K x8
    convmma_kernel<1, false, 2, 1><<<dim3(13, 1, 8), 256, SMEM_T1>>>(
        h1, wk2, zb, part, 1600, 80, 1024, 2, 0, 80, 200);
    reduce_kp2_norms_kernel<<<200, 256>>>(part, kp_b2, keb, nk);

    // ---- join, then Gram + softmax ----
    cudaStreamWaitEvent(0, evQ, 0);
    convmma_kernel<1, false, 1, 0><<<dim3(7, 3, 8), 256, SMEM_T1>>>(
        qeb, keb, zb, G, 800, 200, 128, 2, 200 * 128, 200, 0);
    attn2_kernel<<<800, 256>>>(G, nk, qeb, LP, mask, out);
}